// round 12
// baseline (speedup 1.0000x reference)
#include <cuda_runtime.h>
#include <math.h>

// ---------------- problem constants ----------------
#define Bz   64
#define Tt   800
#define Hh   512
#define SENT 60
#define G4   2048
#define BT   (Bz*Tt)
#define MDNO 121
#define NBLK 128
#define THR  512

typedef unsigned long long u64;

// X: per batch row 8 slices x 72 words (rec/h 64 + misc 8), pitch 580 (%32==4)
#define XP   580
#define SLC  72
// W: [ks][kpair][rp][4] ; per kpair 32 floats: (w(2p,2rp),w(2p+1,2rp),w(2p,2rp+1),w(2p+1,2rp+1))
#define P1KS 1168            // 36 kpairs*32 + 16 pad  (%32==16)
#define P1SZ (8*P1KS)        // 9344
#define P2KS 2192            // 68 kpairs*32 + 16 pad
#define P2SZ (8*P2KS)        // 17536

#define SM_W 0
#define SM_X 17536           // X: 64*580 = 37120
#define SM_G (17536+37120)   // Gm: 2*1280 = 2560 (attention scratch aliases)
#define SM_TOT (SM_G+2560)   // 57216 floats = 228864 B

// ---------------- persistent device scratch ----------------
__device__ float d_hid1[BT*Hh];
__device__ float d_hid2[BT*Hh];
__device__ float d_winA[BT*SENT];
__device__ float d_winB[BT*SENT];
__device__ float d_c1  [Bz*Hh];
__device__ float d_c2  [Bz*Hh];
__device__ float d_kbuf[Bz*10];
__device__ float d_wbuf[Bz*SENT];
__device__ float d_wpA [Bz*SENT];
__device__ float d_wpB [Bz*SENT];

__device__ float d_P1 [NBLK*P1SZ];
__device__ float d_P2 [NBLK*P2SZ];
__device__ float d_b1p[G4];
__device__ float d_b2p[G4];
__device__ float d_Weff[MDNO*1024];

__device__ unsigned          d_cnt[2];
__device__ volatile unsigned d_epoch;

__device__ __forceinline__ float sigf(float x) { return 1.f/(1.f+expf(-x)); }

__device__ __forceinline__ void ffma2(u64& d, u64 a, u64 b) {
    asm("fma.rn.f32x2 %0, %1, %2, %0;" : "+l"(d) : "l"(a), "l"(b));
}

// ---------------- prep kernels ----------------
// decode within-kpair offset q: rp=q>>2, rbit=(q>>1)&1, kbit=q&1 ; r=2*rp+rbit, kl=2*p+kbit
__global__ void prep_pack1(const float* __restrict__ Wih1, const float* __restrict__ Whh1) {
    int idx = blockIdx.x*blockDim.x + threadIdx.x;
    if (idx >= NBLK*P1SZ) return;
    int bb = idx / P1SZ, rem = idx % P1SZ;
    int ks = rem / P1KS, r2 = rem % P1KS;
    float v = 0.f;
    if (r2 < 36*32) {
        int p = r2 >> 5, q = r2 & 31;
        int rp = q >> 2, rbit = (q >> 1) & 1, kbit = q & 1;
        int r = rp*2 + rbit;
        int gate = r >> 2, uu = r & 3;
        int grow = gate*512 + bb*4 + uu;
        int kl = p*2 + kbit;
        if (kl < 64) v = Whh1[grow*512 + ks*64 + kl];
        else { int e = ks*8 + (kl-64); if (e < 63) v = Wih1[grow*63 + e]; }
    }
    d_P1[idx] = v;
}

__global__ void prep_pack2(const float* __restrict__ Wih2, const float* __restrict__ Whh2) {
    int idx = blockIdx.x*blockDim.x + threadIdx.x;
    if (idx >= NBLK*P2SZ) return;
    int bb = idx / P2SZ, rem = idx % P2SZ;
    int ks = rem / P2KS, r2 = rem % P2KS;
    float v = 0.f;
    if (r2 < 68*32) {
        int p = r2 >> 5, q = r2 & 31;
        int rp = q >> 2, rbit = (q >> 1) & 1, kbit = q & 1;
        int r = rp*2 + rbit;
        int gate = r >> 2, uu = r & 3;
        int grow = gate*512 + bb*4 + uu;
        int kl = p*2 + kbit;
        if      (kl < 64) v = Wih2[grow*575 + 3 + ks*64 + kl];
        else if (kl < 72) {
            int e = ks*8 + (kl-64);
            if (e < 3)       v = Wih2[grow*575 + e];
            else if (e < 63) v = Wih2[grow*575 + 515 + (e-3)];
        }
        else              v = Whh2[grow*512 + ks*64 + (kl-72)];
    }
    d_P2[idx] = v;
}

__global__ void prep_misc(const float* __restrict__ bih1, const float* __restrict__ bhh1,
                          const float* __restrict__ bih2, const float* __restrict__ bhh2,
                          const float* __restrict__ Wmdn, const float* __restrict__ w_prev) {
    int idx = blockIdx.x*blockDim.x + threadIdx.x;
    if (idx < MDNO*1024) {
        int o = idx >> 10, k = idx & 1023;
        float v = Wmdn[o*1536 + k];
        if (k >= 512) v += Wmdn[o*1536 + k + 512];
        d_Weff[idx] = v;
    }
    if (idx < G4) {
        int bb = idx >> 4, rr = idx & 15;
        int gate = rr >> 2, uu = rr & 3;
        int grow = gate*512 + bb*4 + uu;
        d_b1p[idx] = bih1[grow] + bhh1[grow];
        d_b2p[idx] = bih2[grow] + bhh2[grow];
    }
    if (idx < Bz*Hh) { d_c1[idx] = 0.f; d_c2[idx] = 0.f; }
    if (idx < Bz*10)   d_kbuf[idx] = 0.f;
    if (idx < Bz*SENT) d_wbuf[idx] = w_prev[idx];
    if (idx == 0) { d_cnt[0] = 0u; d_cnt[1] = 0u; d_epoch = 0u; }
}

// ---------------- split grid barrier ----------------
#define BAR_ARRIVE()                                                          \
    do {                                                                      \
        bseq++;                                                               \
        __syncthreads();                                                      \
        if (tid == 0) {                                                       \
            __threadfence();                                                  \
            if (atomicAdd(&d_cnt[bseq & 1u], 1u) == NBLK - 1u) {              \
                d_cnt[bseq & 1u] = 0u;                                        \
                __threadfence();                                              \
                d_epoch = bseq;                                               \
            }                                                                 \
        }                                                                     \
    } while (0)

#define BAR_WAIT()                                                            \
    do {                                                                      \
        if (tid == 0) {                                                       \
            while ((int)(d_epoch - bseq) < 0) __nanosleep(32);                \
        }                                                                     \
        __syncthreads();                                                      \
    } while (0)

// ---------------- packed MAC: 2 rows x 8 batches per thread ----------------
__device__ __forceinline__ void mac_run2(const float* __restrict__ xr,
                                         const float* __restrict__ wr,
                                         int chunks, u64 (&acc)[8][2])
{
    #pragma unroll 2
    for (int c = 0; c < chunks; c++) {
        double2 wA = *(const double2*)(wr + (2*c+0)*32);
        double2 wB = *(const double2*)(wr + (2*c+1)*32);
        u64 wa0 = __double_as_longlong(wA.x), wa1 = __double_as_longlong(wA.y);
        u64 wb0 = __double_as_longlong(wB.x), wb1 = __double_as_longlong(wB.y);
        #pragma unroll
        for (int j = 0; j < 8; j++) {
            double2 xv = *(const double2*)(xr + j*XP + c*4);
            u64 x0 = __double_as_longlong(xv.x), x1 = __double_as_longlong(xv.y);
            ffma2(acc[j][0], wa0, x0);
            ffma2(acc[j][1], wa1, x0);
            ffma2(acc[j][0], wb0, x1);
            ffma2(acc[j][1], wb1, x1);
        }
    }
}

#define ZERO_ACC(acc)                                                         \
    do { _Pragma("unroll") for (int j = 0; j < 8; j++)                        \
         { acc[j][0] = 0ull; acc[j][1] = 0ull; } } while (0)

// fold even/odd-k halves, reduce over 4 ksl lanes (lane bits 3,4)
#define FOLD_REDUCE(acc, accf)                                                \
    do {                                                                      \
        _Pragma("unroll")                                                     \
        for (int j = 0; j < 8; j++) {                                         \
            _Pragma("unroll")                                                 \
            for (int r = 0; r < 2; r++) {                                     \
                u64 v = acc[j][r];                                            \
                accf[j][r] = __uint_as_float((unsigned)v)                     \
                           + __uint_as_float((unsigned)(v >> 32));            \
            }                                                                 \
        }                                                                     \
        _Pragma("unroll")                                                     \
        for (int off = 8; off <= 16; off <<= 1) {                             \
            _Pragma("unroll")                                                 \
            for (int j = 0; j < 8; j++) {                                     \
                accf[j][0] += __shfl_xor_sync(0xffffffffu, accf[j][0], off);  \
                accf[j][1] += __shfl_xor_sync(0xffffffffu, accf[j][1], off);  \
            }                                                                 \
        }                                                                     \
    } while (0)

// ---------------- persistent main kernel ----------------
extern __shared__ float sm[];

__global__ void __launch_bounds__(THR, 1)
main_scan(const float* __restrict__ strks,
          const float* __restrict__ sents_m,
          const float* __restrict__ onehots,
          const float* __restrict__ Wsw,
          const float* __restrict__ bsw)
{
    float* W  = sm + SM_W;
    float* Xs = sm + SM_X;
    float* Gm = sm + SM_G;
    float* At = Gm;   // attention scratch: shh 512 | pa@512 | pb@520 | pk@528 | wsm@600

    const int tid  = threadIdx.x;
    const int bb   = blockIdx.x;
    const int warp = tid >> 5, lane = tid & 31;
    const int oct  = warp >> 1, kh = warp & 1;
    const int ksl  = lane >> 3, rq = lane & 7;
    const int ks   = kh*4 + ksl;          // 0..7
    const int b0   = oct*8;
    unsigned bseq = 0;

    const int ab = bb & 63;               // attention batch
    const int ah = bb >> 6;               // attention half (components ah*5..ah*5+4)

    // per-position char index + mask, derived ONCE from onehots (float32, safe)
    int chx = 0; float smask = 0.f;
    if (tid < 64) {
        smask = sents_m[ab*64 + tid];
        const float* oh = onehots + (ab*64 + tid)*60;
        for (int c = 0; c < 60; c++) if (oh[c] > 0.5f) chx = c;
    }

    float bi1[4], bi2[4];
    {
        int uu = tid & 3;
        #pragma unroll
        for (int g = 0; g < 4; g++) {
            bi1[g] = d_b1p[bb*16 + g*4 + uu];
            bi2[g] = d_b2p[bb*16 + g*4 + uu];
        }
    }

    const float* xr = Xs + b0*XP + ks*SLC;
    u64 acc[8][2];
    float accf[8][2];

    // ================= phase 1 =================
    {
        const float4* src = (const float4*)(d_P1 + bb*P1SZ);
        for (int i = tid; i < P1SZ/4; i += THR) ((float4*)W)[i] = src[i];
    }
    // t=0 misc fill: strk(0) | w_prev | pad
    for (int i = tid; i < 4096; i += THR) {
        int b2 = i >> 6, e = i & 63;
        float v = 0.f;
        if (e < 3)       v = strks[(b2*Tt + 0)*3 + e];
        else if (e < 63) v = __ldcg(&d_wbuf[b2*60 + e - 3]);
        Xs[b2*XP + (e>>3)*SLC + 64 + (e&7)] = v;
    }
    __syncthreads();

    const float* wr1 = W + ks*P1KS + rq*4;
    ZERO_ACC(acc);     // h1(-1)=0

    for (int t = 0; t < Tt; t++) {
        // misc chunks (x words 64..71 ; w kpairs 32..35)
        mac_run2(xr + 64, wr1 + 32*32, 2, acc);
        FOLD_REDUCE(acc, accf);
        if (lane < 8) {
            #pragma unroll
            for (int j = 0; j < 8; j++)
                *(float2*)&Gm[kh*1280 + (b0+j)*20 + rq*2] =
                    make_float2(accf[j][0], accf[j][1]);
        }
        __syncthreads();
        if (tid < 256) {
            int b2 = tid >> 2, uu = tid & 3;
            int u = bb*4 + uu;
            float ig = Gm[b2*20 +  0 + uu] + Gm[1280 + b2*20 +  0 + uu] + bi1[0];
            float fg = Gm[b2*20 +  4 + uu] + Gm[1280 + b2*20 +  4 + uu] + bi1[1];
            float gg = Gm[b2*20 +  8 + uu] + Gm[1280 + b2*20 +  8 + uu] + bi1[2];
            float og = Gm[b2*20 + 12 + uu] + Gm[1280 + b2*20 + 12 + uu] + bi1[3];
            float c = sigf(fg)*d_c1[b2*512 + u] + sigf(ig)*tanhf(gg);
            float h = sigf(og)*tanhf(c);
            d_c1[b2*512 + u] = c;
            d_hid1[(b2*Tt + t)*512 + u] = h;
        }
        BAR_ARRIVE();          // h1(t) ready
        BAR_WAIT();

        // ---- attention: every block does half the components for batch ab ----
        {
            float* shh = At; float* pa = At+512; float* pb2 = At+520;
            float* pk = At+528; float* wsm = At+600;
            shh[tid] = __ldcg(&d_hid1[(ab*Tt + t)*512 + tid]);
            if (tid < 60) wsm[tid] = 0.f;
            __syncthreads();
            if (warp < 15) {
                int c = warp / 3, which = warp % 3;
                int o = which*10 + ah*5 + c;
                const float* wrow = &Wsw[o*512];
                float s = 0.f;
                #pragma unroll 4
                for (int k2 = lane; k2 < 512; k2 += 32) s += wrow[k2]*shh[k2];
                #pragma unroll
                for (int off = 16; off; off >>= 1) s += __shfl_down_sync(0xffffffffu, s, off);
                if (lane == 0) {
                    s = expf(s + bsw[o]);
                    if (which == 0)      pa[c]  = s;
                    else if (which == 1) pb2[c] = s;
                    else {
                        float kn = d_kbuf[ab*10 + ah*5 + c] + s;
                        pk[c] = kn;
                        d_kbuf[ab*10 + ah*5 + c] = kn;
                    }
                }
            }
            __syncthreads();
            if (tid < 64) {
                float uu = (float)tid, s = 0.f;
                #pragma unroll
                for (int c = 0; c < 5; c++) {
                    float d = pk[c] - uu;
                    s += pa[c]*expf(-pb2[c]*d*d);
                }
                s *= smask;
                atomicAdd(&wsm[chx], s);
            }
            __syncthreads();
            if (tid < 60) {
                float v = wsm[tid];
                if (ah == 0) { d_wpA[ab*60 + tid] = v; d_winA[(ab*Tt + t)*60 + tid] = v; }
                else         { d_wpB[ab*60 + tid] = v; d_winB[(ab*Tt + t)*60 + tid] = v; }
            }
        }
        BAR_ARRIVE();          // w(t) parts ready

        ZERO_ACC(acc);
        if (t + 1 < Tt) {
            // rec fill h1(t) + rec MAC (overlaps bar wait)
            for (int i = tid; i < 8192; i += THR) {
                int b2 = i >> 7, kq = i & 127;
                *(float4*)&Xs[b2*XP + (kq>>4)*SLC + (kq&15)*4] =
                    __ldcg((const float4*)&d_hid1[(b2*Tt + t)*512 + kq*4]);
            }
            __syncthreads();
            mac_run2(xr, wr1, 16, acc);
        }
        BAR_WAIT();
        if (t + 1 < Tt) {
            for (int i = tid; i < 4096; i += THR) {
                int b2 = i >> 6, e = i & 63;
                float v = 0.f;
                if (e < 3)       v = strks[(b2*Tt + t + 1)*3 + e];
                else if (e < 63) v = __ldcg(&d_wpA[b2*60 + e - 3]) + __ldcg(&d_wpB[b2*60 + e - 3]);
                Xs[b2*XP + (e>>3)*SLC + 64 + (e&7)] = v;
            }
        }
        __syncthreads();
    }

    // ================= phase 2 =================
    {
        const float4* src = (const float4*)(d_P2 + bb*P2SZ);
        for (int i = tid; i < P2SZ/4; i += THR) ((float4*)W)[i] = src[i];
    }
    const float* wr2 = W + ks*P2KS + rq*4;
    __syncthreads();

    // preamble: gates(0) = MAC-A(h1(0)) + misc(0)   (h2(-1)=0)
    ZERO_ACC(acc);
    for (int i = tid; i < 8192; i += THR) {
        int b2 = i >> 7, kq = i & 127;
        *(float4*)&Xs[b2*XP + (kq>>4)*SLC + (kq&15)*4] =
            __ldcg((const float4*)&d_hid1[(b2*Tt + 0)*512 + kq*4]);
    }
    __syncthreads();
    mac_run2(xr, wr2, 16, acc);
    for (int i = tid; i < 4096; i += THR) {
        int b2 = i >> 6, e = i & 63;
        float v = 0.f;
        if (e < 3)       v = strks[(b2*Tt + 0)*3 + e];
        else if (e < 63) v = __ldcg(&d_winA[(b2*Tt + 0)*60 + (e-3)]) +
                             __ldcg(&d_winB[(b2*Tt + 0)*60 + (e-3)]);
        Xs[b2*XP + (e>>3)*SLC + 64 + (e&7)] = v;
    }
    __syncthreads();
    mac_run2(xr + 64, wr2 + 32*32, 2, acc);

    for (int t = 0; t < Tt; t++) {
        FOLD_REDUCE(acc, accf);
        if (lane < 8) {
            #pragma unroll
            for (int j = 0; j < 8; j++)
                *(float2*)&Gm[kh*1280 + (b0+j)*20 + rq*2] =
                    make_float2(accf[j][0], accf[j][1]);
        }
        __syncthreads();
        if (tid < 256) {
            int b2 = tid >> 2, uu = tid & 3;
            int u = bb*4 + uu;
            float ig = Gm[b2*20 +  0 + uu] + Gm[1280 + b2*20 +  0 + uu] + bi2[0];
            float fg = Gm[b2*20 +  4 + uu] + Gm[1280 + b2*20 +  4 + uu] + bi2[1];
            float gg = Gm[b2*20 +  8 + uu] + Gm[1280 + b2*20 +  8 + uu] + bi2[2];
            float og = Gm[b2*20 + 12 + uu] + Gm[1280 + b2*20 + 12 + uu] + bi2[3];
            float c = sigf(fg)*d_c2[b2*512 + u] + sigf(ig)*tanhf(gg);
            float h = sigf(og)*tanhf(c);
            d_c2[b2*512 + u] = c;
            d_hid2[(b2*Tt + t)*512 + u] = h;
        }
        if (t + 1 >= Tt) break;

        BAR_ARRIVE();          // h2(t) ready

        // build step t+1: fill h1(t+1) -> MAC-A -> misc fill (overlaps wait)
        ZERO_ACC(acc);
        for (int i = tid; i < 8192; i += THR) {
            int b2 = i >> 7, kq = i & 127;
            *(float4*)&Xs[b2*XP + (kq>>4)*SLC + (kq&15)*4] =
                __ldcg((const float4*)&d_hid1[(b2*Tt + t + 1)*512 + kq*4]);
        }
        __syncthreads();
        mac_run2(xr, wr2, 16, acc);
        for (int i = tid; i < 4096; i += THR) {
            int b2 = i >> 6, e = i & 63;
            float v = 0.f;
            if (e < 3)       v = strks[(b2*Tt + t + 1)*3 + e];
            else if (e < 63) v = __ldcg(&d_winA[(b2*Tt + t + 1)*60 + (e-3)]) +
                                 __ldcg(&d_winB[(b2*Tt + t + 1)*60 + (e-3)]);
            Xs[b2*XP + (e>>3)*SLC + 64 + (e&7)] = v;
        }
        BAR_WAIT();                      // hidden behind fill + MAC-A
        mac_run2(xr + 64, wr2 + 32*32, 2, acc);   // misc
        for (int i = tid; i < 8192; i += THR) {   // fill h2(t)
            int b2 = i >> 7, kq = i & 127;
            *(float4*)&Xs[b2*XP + (kq>>4)*SLC + (kq&15)*4] =
                __ldcg((const float4*)&d_hid2[(b2*Tt + t)*512 + kq*4]);
        }
        __syncthreads();
        mac_run2(xr, wr2 + 36*32, 16, acc);       // MAC-B (h2)
    }
}

// ---------------- MDN head ----------------
__global__ void mdn_kernel(const float* __restrict__ bmdn, float* __restrict__ out)
{
    __shared__ float rows[8*1024];
    __shared__ float pbuf[8*128];
    const int tid  = threadIdx.x;
    const int row0 = blockIdx.x*8;

    for (int idx = tid; idx < 8*1024; idx += 256) {
        int rr = idx >> 10, k2 = idx & 1023;
        int bt = row0 + rr;
        rows[idx] = (k2 < 512) ? d_hid1[bt*512 + k2] : d_hid2[bt*512 + (k2-512)];
    }
    __syncthreads();

    const int o    = tid & 127;
    const int half = tid >> 7;
    if (o < MDNO) {
        float acc[4];
        float bbv = bmdn[o];
        #pragma unroll
        for (int i = 0; i < 4; i++) acc[i] = bbv;
        const float* wr = &d_Weff[o*1024];
        for (int k2 = 0; k2 < 1024; k2 += 4) {
            float4 w = *(const float4*)(wr + k2);
            #pragma unroll
            for (int i = 0; i < 4; i++) {
                const float* x = &rows[(half*4 + i)*1024 + k2];
                acc[i] += w.x*x[0] + w.y*x[1] + w.z*x[2] + w.w*x[3];
            }
        }
        #pragma unroll
        for (int i = 0; i < 4; i++) pbuf[(half*4 + i)*128 + o] = acc[i];
    }
    __syncthreads();

    const int warp = tid >> 5, lane = tid & 31;
    const int bt = row0 + warp;
    const float* p = &pbuf[warp*128];

    float v = (lane < 20) ? p[lane] : -1e30f;
    float mx = v;
    #pragma unroll
    for (int off = 16; off; off >>= 1) mx = fmaxf(mx, __shfl_xor_sync(0xffffffffu, mx, off));
    float e = (lane < 20) ? expf(v - mx) : 0.f;
    float sum = e;
    #pragma unroll
    for (int off = 16; off; off >>= 1) sum += __shfl_xor_sync(0xffffffffu, sum, off);

    if (lane < 20) {
        float* base = out + BT;
        base[            bt*20 + lane] = e / sum;
        base[1*BT*20  +  bt*20 + lane] = p[20 + lane];
        base[2*BT*20  +  bt*20 + lane] = p[40 + lane];
        base[3*BT*20  +  bt*20 + lane] = expf(p[60 + lane]);
        base[4*BT*20  +  bt*20 + lane] = expf(p[80 + lane]);
        base[5*BT*20  +  bt*20 + lane] = tanhf(p[100 + lane]);
    }
    if (lane == 20) out[bt] = 1.f/(1.f + expf(-p[120]));
}

// ---------------- launch ----------------
extern "C" void kernel_launch(void* const* d_in, const int* in_sizes, int n_in,
                              void* d_out, int out_size)
{
    const float* strks   = (const float*)d_in[0];
    const float* sents_m = (const float*)d_in[3];
    const float* onehots = (const float*)d_in[4];
    const float* w_prev  = (const float*)d_in[5];
    const float* Wih1    = (const float*)d_in[6];
    const float* Whh1    = (const float*)d_in[7];
    const float* bih1    = (const float*)d_in[8];
    const float* bhh1    = (const float*)d_in[9];
    const float* Wih2    = (const float*)d_in[10];
    const float* Whh2    = (const float*)d_in[11];
    const float* bih2    = (const float*)d_in[12];
    const float* bhh2    = (const float*)d_in[13];
    const float* Wsw     = (const float*)d_in[14];
    const float* bsw     = (const float*)d_in[15];
    const float* Wmdn    = (const float*)d_in[16];
    const float* bmdn    = (const float*)d_in[17];
    float* out = (float*)d_out;

    cudaFuncSetAttribute(main_scan, cudaFuncAttributeMaxDynamicSharedMemorySize,
                         SM_TOT*sizeof(float));

    prep_pack1<<<(NBLK*P1SZ + 255)/256, 256>>>(Wih1, Whh1);
    prep_pack2<<<(NBLK*P2SZ + 255)/256, 256>>>(Wih2, Whh2);
    prep_misc <<<(MDNO*1024 + 255)/256, 256>>>(bih1, bhh1, bih2, bhh2, Wmdn, w_prev);

    main_scan<<<NBLK, THR, SM_TOT*sizeof(float)>>>(strks, sents_m, onehots, Wsw, bsw);
    mdn_kernel<<<BT/8, 256>>>(bmdn, out);
}

// round 13
// speedup vs baseline: 1.0407x; 1.0407x over previous
#include <cuda_runtime.h>
#include <math.h>

// ---------------- problem constants ----------------
#define Bz   64
#define Tt   800
#define Hh   512
#define SENT 60
#define G4   2048
#define BT   (Bz*Tt)
#define MDNO 121
#define NBLK 128
#define THR  512

// X: per batch row, 16 slices x 36 words (rec/h 32 + misc 4), pitch 580 (%32==4)
#define XP   580
#define SLC  36
// weight layouts [ks][j][16 rows], slice strides %32==16 (conflict-free LDS.128 phases)
#define P1KS 592             // 37*16
#define P1SZ (16*P1KS)       // 9472
#define P2KS 1104            // 69*16
#define P2SZ (16*P2KS)       // 17664

#define SM_W 0
#define SM_X 17664           // X: 64*580 = 37120
#define SM_G (17664+37120)   // Gm: 2*1280 = 2560 (attention scratch aliases)
#define SM_TOT (SM_G+2560)   // 57344 floats = 229376 B

// ---------------- persistent device scratch ----------------
__device__ float d_hid1[BT*Hh];
__device__ float d_hid2[BT*Hh];
__device__ float d_winA[BT*SENT];
__device__ float d_winB[BT*SENT];
__device__ float d_c1  [Bz*Hh];
__device__ float d_c2  [Bz*Hh];
__device__ float d_kbuf[Bz*10];
__device__ float d_wbuf[Bz*SENT];
__device__ float d_wpA [Bz*SENT];
__device__ float d_wpB [Bz*SENT];

__device__ float d_P1 [NBLK*P1SZ];
__device__ float d_P2 [NBLK*P2SZ];
__device__ float d_b1p[G4];
__device__ float d_b2p[G4];
__device__ float d_Weff[MDNO*1024];

__device__ unsigned          d_cnt[2];
__device__ volatile unsigned d_epoch;

__device__ __forceinline__ float sigf(float x) { return 1.f/(1.f+expf(-x)); }

// ---------------- prep kernels ----------------
__global__ void prep_pack1(const float* __restrict__ Wih1, const float* __restrict__ Whh1) {
    int idx = blockIdx.x*blockDim.x + threadIdx.x;
    if (idx >= NBLK*P1SZ) return;
    int bb = idx / P1SZ, rem = idx % P1SZ;
    int ks = rem / P1KS, r2 = rem % P1KS;
    int j = r2 >> 4, rr = r2 & 15;
    int gate = rr >> 2, uu = rr & 3;
    int grow = gate*512 + bb*4 + uu;
    float v = 0.f;
    if (j < 32)      v = Whh1[grow*512 + ks*32 + j];          // recurrent
    else if (j < 36) { int e = ks*4 + (j-32);                  // misc [strk3|win60|pad]
                       if (e < 63) v = Wih1[grow*63 + e]; }
    d_P1[idx] = v;
}

__global__ void prep_pack2(const float* __restrict__ Wih2, const float* __restrict__ Whh2) {
    int idx = blockIdx.x*blockDim.x + threadIdx.x;
    if (idx >= NBLK*P2SZ) return;
    int bb = idx / P2SZ, rem = idx % P2SZ;
    int ks = rem / P2KS, r2 = rem % P2KS;
    int j = r2 >> 4, rr = r2 & 15;
    int gate = rr >> 2, uu = rr & 3;
    int grow = gate*512 + bb*4 + uu;
    float v = 0.f;
    if (j < 32)      v = Wih2[grow*575 + 3 + ks*32 + j];       // h1 (MAC-A)
    else if (j < 36) { int e = ks*4 + (j-32);                   // misc
                       if (e < 3)       v = Wih2[grow*575 + e];
                       else if (e < 63) v = Wih2[grow*575 + 515 + (e-3)]; }
    else if (j < 68) v = Whh2[grow*512 + ks*32 + (j-36)];      // h2 (MAC-B)
    d_P2[idx] = v;
}

__global__ void prep_misc(const float* __restrict__ bih1, const float* __restrict__ bhh1,
                          const float* __restrict__ bih2, const float* __restrict__ bhh2,
                          const float* __restrict__ Wmdn, const float* __restrict__ w_prev) {
    int idx = blockIdx.x*blockDim.x + threadIdx.x;
    if (idx < MDNO*1024) {
        int o = idx >> 10, k = idx & 1023;
        float v = Wmdn[o*1536 + k];
        if (k >= 512) v += Wmdn[o*1536 + k + 512];
        d_Weff[idx] = v;
    }
    if (idx < G4) {
        int bb = idx >> 4, rr = idx & 15;
        int gate = rr >> 2, uu = rr & 3;
        int grow = gate*512 + bb*4 + uu;
        d_b1p[idx] = bih1[grow] + bhh1[grow];
        d_b2p[idx] = bih2[grow] + bhh2[grow];
    }
    if (idx < Bz*Hh) { d_c1[idx] = 0.f; d_c2[idx] = 0.f; }
    if (idx < Bz*10)   d_kbuf[idx] = 0.f;
    if (idx < Bz*SENT) d_wbuf[idx] = w_prev[idx];
    if (idx == 0) { d_cnt[0] = 0u; d_cnt[1] = 0u; d_epoch = 0u; }
}

// ---------------- split grid barrier (tight spin, no nanosleep) ----------------
#define BAR_ARRIVE()                                                          \
    do {                                                                      \
        bseq++;                                                               \
        __syncthreads();                                                      \
        if (tid == 0) {                                                       \
            __threadfence();                                                  \
            if (atomicAdd(&d_cnt[bseq & 1u], 1u) == NBLK - 1u) {              \
                d_cnt[bseq & 1u] = 0u;                                        \
                __threadfence();                                              \
                d_epoch = bseq;                                               \
            }                                                                 \
        }                                                                     \
    } while (0)

#define BAR_WAIT()                                                            \
    do {                                                                      \
        if (tid == 0) {                                                       \
            while ((int)(d_epoch - bseq) < 0) { }                             \
        }                                                                     \
        __syncthreads();                                                      \
    } while (0)

// ---------------- MAC: 4 rows x 8 batch-cols over chunks of 4 k ----------------
__device__ __forceinline__ void mac_run(const float* __restrict__ xr,
                                        const float* __restrict__ wr,
                                        int chunks, float (&acc)[8][4])
{
    #pragma unroll 2
    for (int c = 0; c < chunks; c++) {
        int k = c*4;
        float4 w0 = *(const float4*)(wr + (k+0)*16);
        float4 w1 = *(const float4*)(wr + (k+1)*16);
        float4 w2 = *(const float4*)(wr + (k+2)*16);
        float4 w3 = *(const float4*)(wr + (k+3)*16);
        #pragma unroll
        for (int j = 0; j < 8; j++) {
            float4 xv = *(const float4*)(xr + j*XP + k);
            acc[j][0] = fmaf(w0.x, xv.x, fmaf(w1.x, xv.y, fmaf(w2.x, xv.z, fmaf(w3.x, xv.w, acc[j][0]))));
            acc[j][1] = fmaf(w0.y, xv.x, fmaf(w1.y, xv.y, fmaf(w2.y, xv.z, fmaf(w3.y, xv.w, acc[j][1]))));
            acc[j][2] = fmaf(w0.z, xv.x, fmaf(w1.z, xv.y, fmaf(w2.z, xv.z, fmaf(w3.z, xv.w, acc[j][2]))));
            acc[j][3] = fmaf(w0.w, xv.x, fmaf(w1.w, xv.y, fmaf(w2.w, xv.z, fmaf(w3.w, xv.w, acc[j][3]))));
        }
    }
}

#define ZERO_ACC(acc)                                                         \
    do { _Pragma("unroll") for (int j = 0; j < 8; j++)                        \
         { _Pragma("unroll") for (int i = 0; i < 4; i++) acc[j][i] = 0.f; } } while (0)

#define KS_REDUCE(acc)                                                        \
    do {                                                                      \
        _Pragma("unroll")                                                     \
        for (int off = 4; off <= 16; off <<= 1) {                             \
            _Pragma("unroll")                                                 \
            for (int j = 0; j < 8; j++) {                                     \
                _Pragma("unroll")                                             \
                for (int i = 0; i < 4; i++)                                   \
                    acc[j][i] += __shfl_xor_sync(0xffffffffu, acc[j][i], off);\
            }                                                                 \
        }                                                                     \
    } while (0)

// ---------------- persistent main kernel ----------------
extern __shared__ float sm[];

__global__ void __launch_bounds__(THR, 1)
main_scan(const float* __restrict__ strks,
          const float* __restrict__ sents_m,
          const float* __restrict__ onehots,
          const float* __restrict__ Wsw,
          const float* __restrict__ bsw)
{
    float* W   = sm + SM_W;
    float* Xs  = sm + SM_X;
    float* Gm  = sm + SM_G;          // [2][64*20]
    float* At  = Gm;                 // attn scratch: shh 512 | pa@512 | pb@520 | pk@528 | wsm@600
    float* Wsm = W + P1SZ;           // 8192 free floats during phase 1: 15x512 Wsw rows + 15 bias

    const int tid  = threadIdx.x;
    const int bb   = blockIdx.x;
    const int warp = tid >> 5, lane = tid & 31;
    const int oct  = warp >> 1, kh = warp & 1;
    const int ksl  = lane >> 2, rq = lane & 3;
    const int ks   = kh*8 + ksl;
    const int b0   = oct*8;
    unsigned bseq = 0;

    const int ab = bb & 63;          // attention batch
    const int ah = bb >> 6;          // attention half (components ah*5..ah*5+4)

    // per-position char index + mask, derived once from onehots
    int chx = 0; float smask = 0.f;
    if (tid < 64) {
        smask = sents_m[ab*64 + tid];
        const float* oh = onehots + (ab*64 + tid)*60;
        for (int c = 0; c < 60; c++) if (oh[c] > 0.5f) chx = c;
    }

    float bi1[4], bi2[4];
    {
        int uu = tid & 3;
        #pragma unroll
        for (int g = 0; g < 4; g++) {
            bi1[g] = d_b1p[bb*16 + g*4 + uu];
            bi2[g] = d_b2p[bb*16 + g*4 + uu];
        }
    }

    const float* xr = Xs + b0*XP + ks*SLC;
    float acc[8][4];

    // ================= phase 1 =================
    {
        const float4* src = (const float4*)(d_P1 + bb*P1SZ);
        for (int i = tid; i < P1SZ/4; i += THR) ((float4*)W)[i] = src[i];
    }
    // stage this block's 15 Wsw rows + biases into smem
    for (int i = tid; i < 15*128; i += THR) {
        int row = i >> 7, c4 = i & 127;
        int which = row / 5, cc = row % 5;
        int o = which*10 + ah*5 + cc;
        ((float4*)(Wsm + row*512))[c4] = *(const float4*)&Wsw[o*512 + c4*4];
    }
    if (tid < 15) {
        int which = tid / 5, cc = tid % 5;
        Wsm[15*512 + tid] = bsw[which*10 + ah*5 + cc];
    }
    // t=0 misc fill: strk(0) | w_prev | pad
    for (int i = tid; i < 4096; i += THR) {
        int b2 = i >> 6, e = i & 63;
        float v = 0.f;
        if (e < 3)       v = strks[(b2*Tt + 0)*3 + e];
        else if (e < 63) v = __ldcg(&d_wbuf[b2*60 + e - 3]);
        Xs[b2*XP + (e>>2)*SLC + 32 + (e&3)] = v;
    }
    __syncthreads();

    const float* wr1 = W + ks*P1KS + rq*4;
    ZERO_ACC(acc);     // h1(-1)=0

    for (int t = 0; t < Tt; t++) {
        // misc chunk (j32..35)
        mac_run(xr + 32, wr1 + 32*16, 1, acc);
        KS_REDUCE(acc);
        if (lane < 4) {
            #pragma unroll
            for (int j = 0; j < 8; j++)
                *(float4*)&Gm[kh*1280 + (b0+j)*20 + rq*4] =
                    make_float4(acc[j][0], acc[j][1], acc[j][2], acc[j][3]);
        }
        __syncthreads();
        if (tid < 256) {
            int b2 = tid >> 2, uu = tid & 3;
            int u = bb*4 + uu;
            float ig = Gm[b2*20 +  0 + uu] + Gm[1280 + b2*20 +  0 + uu] + bi1[0];
            float fg = Gm[b2*20 +  4 + uu] + Gm[1280 + b2*20 +  4 + uu] + bi1[1];
            float gg = Gm[b2*20 +  8 + uu] + Gm[1280 + b2*20 +  8 + uu] + bi1[2];
            float og = Gm[b2*20 + 12 + uu] + Gm[1280 + b2*20 + 12 + uu] + bi1[3];
            float c = sigf(fg)*d_c1[b2*512 + u] + sigf(ig)*tanhf(gg);
            float h = sigf(og)*tanhf(c);
            d_c1[b2*512 + u] = c;
            d_hid1[(b2*Tt + t)*512 + u] = h;
        }
        BAR_ARRIVE();          // h1(t) ready
        BAR_WAIT();

        // ---- attention: every block does 5 components for batch ab ----
        {
            float* shh = At; float* pa = At+512; float* pb2 = At+520;
            float* pk = At+528; float* wsm = At+600;
            shh[tid] = __ldcg(&d_hid1[(ab*Tt + t)*512 + tid]);
            if (tid < 60) wsm[tid] = 0.f;
            __syncthreads();
            if (warp < 15) {
                int c = warp / 3, which = warp % 3;
                const float* wrow = Wsm + (which*5 + c)*512;
                float s = 0.f;
                #pragma unroll 4
                for (int k2 = lane; k2 < 512; k2 += 32) s += wrow[k2]*shh[k2];
                #pragma unroll
                for (int off = 16; off; off >>= 1) s += __shfl_down_sync(0xffffffffu, s, off);
                if (lane == 0) {
                    s = expf(s + Wsm[15*512 + which*5 + c]);
                    if (which == 0)      pa[c]  = s;
                    else if (which == 1) pb2[c] = s;
                    else {
                        float kn = d_kbuf[ab*10 + ah*5 + c] + s;
                        pk[c] = kn;
                        d_kbuf[ab*10 + ah*5 + c] = kn;
                    }
                }
            }
            __syncthreads();
            if (tid < 64) {
                float uu = (float)tid, s = 0.f;
                #pragma unroll
                for (int c = 0; c < 5; c++) {
                    float d = pk[c] - uu;
                    s += pa[c]*expf(-pb2[c]*d*d);
                }
                s *= smask;
                atomicAdd(&wsm[chx], s);
            }
            __syncthreads();
            if (tid < 60) {
                float v = wsm[tid];
                if (ah == 0) { d_wpA[ab*60 + tid] = v; d_winA[(ab*Tt + t)*60 + tid] = v; }
                else         { d_wpB[ab*60 + tid] = v; d_winB[(ab*Tt + t)*60 + tid] = v; }
            }
        }
        BAR_ARRIVE();          // w(t) ready (arrive early; overlap below)

        ZERO_ACC(acc);
        if (t + 1 < Tt) {
            // rec fill h1(t) + rec MAC (overlaps bar wait)
            for (int i = tid; i < 8192; i += THR) {
                int b2 = i >> 7, kq = i & 127;
                *(float4*)&Xs[b2*XP + (kq>>3)*SLC + (kq&7)*4] =
                    __ldcg((const float4*)&d_hid1[(b2*Tt + t)*512 + kq*4]);
            }
            __syncthreads();
            mac_run(xr, wr1, 8, acc);
        }
        BAR_WAIT();            // hidden behind rec MAC
        if (t + 1 < Tt) {
            for (int i = tid; i < 4096; i += THR) {
                int b2 = i >> 6, e = i & 63;
                float v = 0.f;
                if (e < 3)       v = strks[(b2*Tt + t + 1)*3 + e];
                else if (e < 63) v = __ldcg(&d_wpA[b2*60 + e - 3]) + __ldcg(&d_wpB[b2*60 + e - 3]);
                Xs[b2*XP + (e>>2)*SLC + 32 + (e&3)] = v;
            }
        }
        __syncthreads();
    }

    // ================= phase 2 =================
    {
        const float4* src = (const float4*)(d_P2 + bb*P2SZ);
        for (int i = tid; i < P2SZ/4; i += THR) ((float4*)W)[i] = src[i];
    }
    const float* wr2 = W + ks*P2KS + rq*4;
    __syncthreads();

    // preamble: gates(0) = MAC-A(h1(0)) + misc(0)   (h2(-1)=0)
    ZERO_ACC(acc);
    for (int i = tid; i < 8192; i += THR) {
        int b2 = i >> 7, kq = i & 127;
        *(float4*)&Xs[b2*XP + (kq>>3)*SLC + (kq&7)*4] =
            __ldcg((const float4*)&d_hid1[(b2*Tt + 0)*512 + kq*4]);
    }
    __syncthreads();
    mac_run(xr, wr2, 8, acc);
    for (int i = tid; i < 4096; i += THR) {
        int b2 = i >> 6, e = i & 63;
        float v = 0.f;
        if (e < 3)       v = strks[(b2*Tt + 0)*3 + e];
        else if (e < 63) v = __ldcg(&d_winA[(b2*Tt + 0)*60 + (e-3)]) +
                             __ldcg(&d_winB[(b2*Tt + 0)*60 + (e-3)]);
        Xs[b2*XP + (e>>2)*SLC + 32 + (e&3)] = v;
    }
    __syncthreads();
    mac_run(xr + 32, wr2 + 32*16, 1, acc);

    for (int t = 0; t < Tt; t++) {
        KS_REDUCE(acc);
        if (lane < 4) {
            #pragma unroll
            for (int j = 0; j < 8; j++)
                *(float4*)&Gm[kh*1280 + (b0+j)*20 + rq*4] =
                    make_float4(acc[j][0], acc[j][1], acc[j][2], acc[j][3]);
        }
        __syncthreads();
        if (tid < 256) {
            int b2 = tid >> 2, uu = tid & 3;
            int u = bb*4 + uu;
            float ig = Gm[b2*20 +  0 + uu] + Gm[1280 + b2*20 +  0 + uu] + bi2[0];
            float fg = Gm[b2*20 +  4 + uu] + Gm[1280 + b2*20 +  4 + uu] + bi2[1];
            float gg = Gm[b2*20 +  8 + uu] + Gm[1280 + b2*20 +  8 + uu] + bi2[2];
            float og = Gm[b2*20 + 12 + uu] + Gm[1280 + b2*20 + 12 + uu] + bi2[3];
            float c = sigf(fg)*d_c2[b2*512 + u] + sigf(ig)*tanhf(gg);
            float h = sigf(og)*tanhf(c);
            d_c2[b2*512 + u] = c;
            d_hid2[(b2*Tt + t)*512 + u] = h;
        }
        if (t + 1 >= Tt) break;

        BAR_ARRIVE();          // h2(t) ready

        // build step t+1: fill h1(t+1) -> MAC-A -> misc fill (overlaps wait)
        ZERO_ACC(acc);
        for (int i = tid; i < 8192; i += THR) {
            int b2 = i >> 7, kq = i & 127;
            *(float4*)&Xs[b2*XP + (kq>>3)*SLC + (kq&7)*4] =
                __ldcg((const float4*)&d_hid1[(b2*Tt + t + 1)*512 + kq*4]);
        }
        __syncthreads();
        mac_run(xr, wr2, 8, acc);
        for (int i = tid; i < 4096; i += THR) {
            int b2 = i >> 6, e = i & 63;
            float v = 0.f;
            if (e < 3)       v = strks[(b2*Tt + t + 1)*3 + e];
            else if (e < 63) v = __ldcg(&d_winA[(b2*Tt + t + 1)*60 + (e-3)]) +
                                 __ldcg(&d_winB[(b2*Tt + t + 1)*60 + (e-3)]);
            Xs[b2*XP + (e>>2)*SLC + 32 + (e&3)] = v;
        }
        BAR_WAIT();                      // hidden behind fill + MAC-A
        mac_run(xr + 32, wr2 + 32*16, 1, acc);    // misc
        for (int i = tid; i < 8192; i += THR) {   // fill h2(t)
            int b2 = i >> 7, kq = i & 127;
            *(float4*)&Xs[b2*XP + (kq>>3)*SLC + (kq&7)*4] =
                __ldcg((const float4*)&d_hid2[(b2*Tt + t)*512 + kq*4]);
        }
        __syncthreads();
        mac_run(xr, wr2 + 36*16, 8, acc);         // MAC-B (h2)
    }
}

// ---------------- MDN head ----------------
__global__ void mdn_kernel(const float* __restrict__ bmdn, float* __restrict__ out)
{
    __shared__ float rows[8*1024];
    __shared__ float pbuf[8*128];
    const int tid  = threadIdx.x;
    const int row0 = blockIdx.x*8;

    for (int idx = tid; idx < 8*1024; idx += 256) {
        int rr = idx >> 10, k2 = idx & 1023;
        int bt = row0 + rr;
        rows[idx] = (k2 < 512) ? d_hid1[bt*512 + k2] : d_hid2[bt*512 + (k2-512)];
    }
    __syncthreads();

    const int o    = tid & 127;
    const int half = tid >> 7;
    if (o < MDNO) {
        float acc[4];
        float bbv = bmdn[o];
        #pragma unroll
        for (int i = 0; i < 4; i++) acc[i] = bbv;
        const float* wr = &d_Weff[o*1024];
        for (int k2 = 0; k2 < 1024; k2 += 4) {
            float4 w = *(const float4*)(wr + k2);
            #pragma unroll
            for (int i = 0; i < 4; i++) {
                const float* x = &rows[(half*4 + i)*1024 + k2];
                acc[i] += w.x*x[0] + w.y*x[1] + w.z*x[2] + w.w*x[3];
            }
        }
        #pragma unroll
        for (int i = 0; i < 4; i++) pbuf[(half*4 + i)*128 + o] = acc[i];
    }
    __syncthreads();

    const int warp = tid >> 5, lane = tid & 31;
    const int bt = row0 + warp;
    const float* p = &pbuf[warp*128];

    float v = (lane < 20) ? p[lane] : -1e30f;
    float mx = v;
    #pragma unroll
    for (int off = 16; off; off >>= 1) mx = fmaxf(mx, __shfl_xor_sync(0xffffffffu, mx, off));
    float e = (lane < 20) ? expf(v - mx) : 0.f;
    float sum = e;
    #pragma unroll
    for (int off = 16; off; off >>= 1) sum += __shfl_xor_sync(0xffffffffu, sum, off);

    if (lane < 20) {
        float* base = out + BT;
        base[            bt*20 + lane] = e / sum;
        base[1*BT*20  +  bt*20 + lane] = p[20 + lane];
        base[2*BT*20  +  bt*20 + lane] = p[40 + lane];
        base[3*BT*20  +  bt*20 + lane] = expf(p[60 + lane]);
        base[4*BT*20  +  bt*20 + lane] = expf(p[80 + lane]);
        base[5*BT*20  +  bt*20 + lane] = tanhf(p[100 + lane]);
    }
    if (lane == 20) out[bt] = 1.f/(1.f + expf(-p[120]));
}

// ---------------- launch ----------------
extern "C" void kernel_launch(void* const* d_in, const int* in_sizes, int n_in,
                              void* d_out, int out_size)
{
    const float* strks   = (const float*)d_in[0];
    const float* sents_m = (const float*)d_in[3];
    const float* onehots = (const float*)d_in[4];
    const float* w_prev  = (const float*)d_in[5];
    const float* Wih1    = (const float*)d_in[6];
    const float* Whh1    = (const float*)d_in[7];
    const float* bih1    = (const float*)d_in[8];
    const float* bhh1    = (const float*)d_in[9];
    const float* Wih2    = (const float*)d_in[10];
    const float* Whh2    = (const float*)d_in[11];
    const float* bih2    = (const float*)d_in[12];
    const float* bhh2    = (const float*)d_in[13];
    const float* Wsw     = (const float*)d_in[14];
    const float* bsw     = (const float*)d_in[15];
    const float* Wmdn    = (const float*)d_in[16];
    const float* bmdn    = (const float*)d_in[17];
    float* out = (float*)d_out;

    cudaFuncSetAttribute(main_scan, cudaFuncAttributeMaxDynamicSharedMemorySize,
                         SM_TOT*sizeof(float));

    prep_pack1<<<(NBLK*P1SZ + 255)/256, 256>>>(Wih1, Whh1);
    prep_pack2<<<(NBLK*P2SZ + 255)/256, 256>>>(Wih2, Whh2);
    prep_misc <<<(MDNO*1024 + 255)/256, 256>>>(bih1, bhh1, bih2, bhh2, Wmdn, w_prev);

    main_scan<<<NBLK, THR, SM_TOT*sizeof(float)>>>(strks, sents_m, onehots, Wsw, bsw);
    mdn_kernel<<<BT/8, 256>>>(bmdn, out);
}

// round 14
// speedup vs baseline: 1.3543x; 1.3014x over previous
#include <cuda_runtime.h>
#include <math.h>

// ---------------- problem constants ----------------
#define Bz   64
#define Tt   800
#define Hh   512
#define SENT 60
#define G4   2048
#define BT   (Bz*Tt)
#define MDNO 121
#define NBLK 128
#define THR  512

// X: per batch row, 16 slices x 36 words (h 32 + misc1 4), pitch 580 (%32==4)
#define XP   580
#define SLC  36
// W1 smem layout [ks][j][16 rows], slice stride %32==16 (conflict-free quarter-warp LDS.128)
#define P1KS 592             // 37*16
#define P1SZ (16*P1KS)       // 9472
// W2 gmem layout (streamed): float4 idx = ((c*4+r)*2 + kh)*32 + ksl*4 + rq ; 17 chunks
#define P2WSZ 17408          // floats per block

// dynamic smem (floats)
#define SM_W1 0
#define SM_X  9472           // 64*580 = 37120
#define SM_M2 (9472+37120)   // 64*68 = 4352
#define SM_G  (SM_M2+4352)   // 2*1280 = 2560 (attention scratch aliases)
#define SM_TOT (SM_G+2560)   // 53504 floats = 214016 B

// ---------------- persistent device scratch ----------------
__device__ float d_hid1[BT*Hh];
__device__ float d_hid2[BT*Hh];
__device__ float d_c1  [Bz*Hh];
__device__ float d_c2  [Bz*Hh];
__device__ float d_kbuf[Bz*10];
__device__ float d_wbuf[Bz*SENT];
__device__ float d_wpA [Bz*SENT];
__device__ float d_wpB [Bz*SENT];

__device__ float d_P1 [NBLK*P1SZ];
__device__ float d_P2w[NBLK*P2WSZ];
__device__ float d_b1p[G4];
__device__ float d_b2p[G4];
__device__ float d_Weff[MDNO*1024];

__device__ unsigned          d_cnt[2];
__device__ volatile unsigned d_epoch;

__device__ __forceinline__ float sigf(float x) { return 1.f/(1.f+expf(-x)); }

// ---------------- prep kernels ----------------
__global__ void prep_pack1(const float* __restrict__ Wih1, const float* __restrict__ Whh1) {
    int idx = blockIdx.x*blockDim.x + threadIdx.x;
    if (idx >= NBLK*P1SZ) return;
    int bb = idx / P1SZ, rem = idx % P1SZ;
    int ks = rem / P1KS, r2 = rem % P1KS;
    int j = r2 >> 4, rr = r2 & 15;
    int gate = rr >> 2, uu = rr & 3;
    int grow = gate*512 + bb*4 + uu;
    float v = 0.f;
    if (j < 32)      v = Whh1[grow*512 + ks*32 + j];          // recurrent h1
    else if (j < 36) { int e = ks*4 + (j-32);                  // misc [strk3|win60|pad]
                       if (e < 63) v = Wih1[grow*63 + e]; }
    d_P1[idx] = v;
}

// W2 streamed layout: chunks 0..7 = h1 part, 8 = misc2, 9..16 = h2 part
__global__ void prep_pack2w(const float* __restrict__ Wih2, const float* __restrict__ Whh2) {
    int idx = blockIdx.x*blockDim.x + threadIdx.x;
    if (idx >= NBLK*P2WSZ) return;
    int bb = idx / P2WSZ, rem = idx % P2WSZ;
    int f   = rem & 3;
    int i4  = rem >> 2;
    int rq  = i4 & 3;
    int ksl = (i4 >> 2) & 7;
    int kh  = (i4 >> 5) & 1;
    int cr  = i4 >> 6;
    int r   = cr & 3;
    int c   = cr >> 2;            // 0..16
    int ks  = kh*8 + ksl;
    int row16 = rq*4 + f;
    int gate = row16 >> 2, uu = row16 & 3;
    int grow = gate*512 + bb*4 + uu;
    float v = 0.f;
    if (c < 8)       v = Wih2[grow*575 + 3 + ks*32 + c*4 + r];
    else if (c == 8) {
        int e = ks*4 + r;
        if (e < 3)       v = Wih2[grow*575 + e];
        else if (e < 63) v = Wih2[grow*575 + 515 + (e-3)];
    }
    else             v = Whh2[grow*512 + ks*32 + (c-9)*4 + r];
    d_P2w[idx] = v;
}

__global__ void prep_misc(const float* __restrict__ bih1, const float* __restrict__ bhh1,
                          const float* __restrict__ bih2, const float* __restrict__ bhh2,
                          const float* __restrict__ Wmdn, const float* __restrict__ w_prev) {
    int idx = blockIdx.x*blockDim.x + threadIdx.x;
    if (idx < MDNO*1024) {
        int o = idx >> 10, k = idx & 1023;
        float v = Wmdn[o*1536 + k];
        if (k >= 512) v += Wmdn[o*1536 + k + 512];
        d_Weff[idx] = v;
    }
    if (idx < G4) {
        int bb = idx >> 4, rr = idx & 15;
        int gate = rr >> 2, uu = rr & 3;
        int grow = gate*512 + bb*4 + uu;
        d_b1p[idx] = bih1[grow] + bhh1[grow];
        d_b2p[idx] = bih2[grow] + bhh2[grow];
    }
    if (idx < Bz*Hh) { d_c1[idx] = 0.f; d_c2[idx] = 0.f; }
    if (idx < Bz*10)   d_kbuf[idx] = 0.f;
    if (idx < Bz*SENT) d_wbuf[idx] = w_prev[idx];
    if (idx == 0) { d_cnt[0] = 0u; d_cnt[1] = 0u; d_epoch = 0u; }
}

// ---------------- split grid barrier ----------------
#define BAR_ARRIVE()                                                          \
    do {                                                                      \
        bseq++;                                                               \
        __syncthreads();                                                      \
        if (tid == 0) {                                                       \
            __threadfence();                                                  \
            if (atomicAdd(&d_cnt[bseq & 1u], 1u) == NBLK - 1u) {              \
                d_cnt[bseq & 1u] = 0u;                                        \
                __threadfence();                                              \
                d_epoch = bseq;                                               \
            }                                                                 \
        }                                                                     \
    } while (0)

#define BAR_WAIT()                                                            \
    do {                                                                      \
        if (tid == 0) {                                                       \
            while ((int)(d_epoch - bseq) < 0) __nanosleep(32);                \
        }                                                                     \
        __syncthreads();                                                      \
    } while (0)

// ---------------- MAC (smem weights): 4 rows x 8 batches per chunk of 4 k ----
__device__ __forceinline__ void mac_run(const float* __restrict__ xr,
                                        const float* __restrict__ wr,
                                        int chunks, float (&acc)[8][4])
{
    #pragma unroll 2
    for (int c = 0; c < chunks; c++) {
        int k = c*4;
        float4 w0 = *(const float4*)(wr + (k+0)*16);
        float4 w1 = *(const float4*)(wr + (k+1)*16);
        float4 w2 = *(const float4*)(wr + (k+2)*16);
        float4 w3 = *(const float4*)(wr + (k+3)*16);
        #pragma unroll
        for (int j = 0; j < 8; j++) {
            float4 xv = *(const float4*)(xr + j*XP + k);
            acc[j][0] = fmaf(w0.x, xv.x, fmaf(w1.x, xv.y, fmaf(w2.x, xv.z, fmaf(w3.x, xv.w, acc[j][0]))));
            acc[j][1] = fmaf(w0.y, xv.x, fmaf(w1.y, xv.y, fmaf(w2.y, xv.z, fmaf(w3.y, xv.w, acc[j][1]))));
            acc[j][2] = fmaf(w0.z, xv.x, fmaf(w1.z, xv.y, fmaf(w2.z, xv.z, fmaf(w3.z, xv.w, acc[j][2]))));
            acc[j][3] = fmaf(w0.w, xv.x, fmaf(w1.w, xv.y, fmaf(w2.w, xv.z, fmaf(w3.w, xv.w, acc[j][3]))));
        }
    }
}

// ---------------- MAC (gmem-streamed weights) ----------------
// wt = per-thread float4 base (includes kh/ksl/rq); chunk stride 256 float4
__device__ __forceinline__ void mac2g(const float4* __restrict__ wt, int c0,
                                      const float* __restrict__ xr, int xpitch,
                                      int nch, float (&acc)[8][4])
{
    #pragma unroll 4
    for (int c = 0; c < nch; c++) {
        const float4* wp = wt + (c0 + c)*256;
        float4 w0 = __ldcg(wp);
        float4 w1 = __ldcg(wp + 64);
        float4 w2 = __ldcg(wp + 128);
        float4 w3 = __ldcg(wp + 192);
        #pragma unroll
        for (int j = 0; j < 8; j++) {
            float4 xv = *(const float4*)(xr + j*xpitch + c*4);
            acc[j][0] = fmaf(w0.x, xv.x, fmaf(w1.x, xv.y, fmaf(w2.x, xv.z, fmaf(w3.x, xv.w, acc[j][0]))));
            acc[j][1] = fmaf(w0.y, xv.x, fmaf(w1.y, xv.y, fmaf(w2.y, xv.z, fmaf(w3.y, xv.w, acc[j][1]))));
            acc[j][2] = fmaf(w0.z, xv.x, fmaf(w1.z, xv.y, fmaf(w2.z, xv.z, fmaf(w3.z, xv.w, acc[j][2]))));
            acc[j][3] = fmaf(w0.w, xv.x, fmaf(w1.w, xv.y, fmaf(w2.w, xv.z, fmaf(w3.w, xv.w, acc[j][3]))));
        }
    }
}

#define ZERO_ACC(acc)                                                         \
    do { _Pragma("unroll") for (int j = 0; j < 8; j++)                        \
         { _Pragma("unroll") for (int i = 0; i < 4; i++) acc[j][i] = 0.f; } } while (0)

#define KS_REDUCE(acc)                                                        \
    do {                                                                      \
        _Pragma("unroll")                                                     \
        for (int off = 4; off <= 16; off <<= 1) {                             \
            _Pragma("unroll")                                                 \
            for (int j = 0; j < 8; j++) {                                     \
                _Pragma("unroll")                                             \
                for (int i = 0; i < 4; i++)                                   \
                    acc[j][i] += __shfl_xor_sync(0xffffffffu, acc[j][i], off);\
            }                                                                 \
        }                                                                     \
    } while (0)

#define GM_STORE(acc)                                                         \
    do { if (lane < 4) {                                                      \
        _Pragma("unroll")                                                     \
        for (int j = 0; j < 8; j++)                                           \
            *(float4*)&Gm[kh*1280 + (b0+j)*20 + rq*4] =                       \
                make_float4(acc[j][0], acc[j][1], acc[j][2], acc[j][3]);      \
    } } while (0)

// ---------------- persistent main kernel ----------------
extern __shared__ float sm[];

__global__ void __launch_bounds__(THR, 1)
main_scan(const float* __restrict__ strks,
          const float* __restrict__ sents_m,
          const float* __restrict__ onehots,
          const float* __restrict__ Wsw,
          const float* __restrict__ bsw)
{
    float* W1  = sm + SM_W1;
    float* Xs  = sm + SM_X;
    float* M2s = sm + SM_M2;
    float* Gm  = sm + SM_G;          // [2][64*20]
    float* At  = Gm;                 // attn scratch: shh 512 | pa@512 | pb@520 | pk@528 | wsm@600

    const int tid  = threadIdx.x;
    const int bb   = blockIdx.x;
    const int warp = tid >> 5, lane = tid & 31;
    const int oct  = warp >> 1, kh = warp & 1;
    const int ksl  = lane >> 2, rq = lane & 3;
    const int ks   = kh*8 + ksl;
    const int b0   = oct*8;
    unsigned bseq = 0;

    const int ab = bb & 63;          // attention batch
    const int ah = bb >> 6;          // attention half (components ah*5..ah*5+4)

    int chx = 0; float smask = 0.f;
    if (tid < 64) {
        smask = sents_m[ab*64 + tid];
        const float* oh = onehots + (ab*64 + tid)*60;
        for (int c = 0; c < 60; c++) if (oh[c] > 0.5f) chx = c;
    }

    float bi1[4], bi2[4];
    {
        int uu = tid & 3;
        #pragma unroll
        for (int g = 0; g < 4; g++) {
            bi1[g] = d_b1p[bb*16 + g*4 + uu];
            bi2[g] = d_b2p[bb*16 + g*4 + uu];
        }
    }

    const float*  xrX = Xs  + b0*XP + ks*SLC;
    const float*  xrM = M2s + b0*68 + ks*4;
    const float*  wr1 = W1  + ks*P1KS + rq*4;
    const float4* wt  = (const float4*)d_P2w + (size_t)bb*(P2WSZ/4) + kh*32 + ksl*4 + rq;

    float acc[8][4];

    // ---------- prologue ----------
    {
        const float4* src = (const float4*)(d_P1 + bb*P1SZ);
        for (int i = tid; i < P1SZ/4; i += THR) ((float4*)W1)[i] = src[i];
    }
    for (int i = tid; i < 8192; i += THR) {                       // X.h = 0
        int b2 = i >> 7, kq = i & 127;
        *(float4*)&Xs[b2*XP + (kq>>3)*SLC + (kq&7)*4] = make_float4(0.f,0.f,0.f,0.f);
    }
    for (int i = tid; i < 4096; i += THR) {                       // misc1 = [strk(0)|w_prev]
        int b2 = i >> 6, e = i & 63;
        float v = 0.f;
        if (e < 3)       v = strks[(b2*Tt + 0)*3 + e];
        else if (e < 63) v = __ldcg(&d_wbuf[b2*60 + e - 3]);
        Xs[b2*XP + (e>>2)*SLC + 32 + (e&3)] = v;
    }
    __syncthreads();

    // ---------- merged scan ----------
    for (int t = 0; t < Tt; t++) {
        // LSTM1 gates(t): rec over X.h=h1(t-1) + misc1
        ZERO_ACC(acc);
        mac_run(xrX, wr1, 8, acc);
        mac_run(xrX + 32, wr1 + 32*16, 1, acc);
        KS_REDUCE(acc);
        GM_STORE(acc);
        __syncthreads();
        if (tid < 256) {
            int b2 = tid >> 2, uu = tid & 3;
            int u = bb*4 + uu;
            float ig = Gm[b2*20 +  0 + uu] + Gm[1280 + b2*20 +  0 + uu] + bi1[0];
            float fg = Gm[b2*20 +  4 + uu] + Gm[1280 + b2*20 +  4 + uu] + bi1[1];
            float gg = Gm[b2*20 +  8 + uu] + Gm[1280 + b2*20 +  8 + uu] + bi1[2];
            float og = Gm[b2*20 + 12 + uu] + Gm[1280 + b2*20 + 12 + uu] + bi1[3];
            float c = sigf(fg)*d_c1[b2*512 + u] + sigf(ig)*tanhf(gg);
            float h = sigf(og)*tanhf(c);
            d_c1[b2*512 + u] = c;
            d_hid1[(b2*Tt + t)*512 + u] = h;
        }
        BAR_ARRIVE();                 // A: h1(t) ready

        // LSTM2 gates(t-1) — hides bar A skew
        if (t > 0) {
            ZERO_ACC(acc);
            mac2g(wt, 0, xrX, XP, 8, acc);      // W2A over h1(t-1)
            mac2g(wt, 8, xrM, 68, 1, acc);      // misc2(t-1)
            __syncthreads();                     // all done reading X.h
            for (int i = tid; i < 8192; i += THR) {   // X.h <- h2(t-2)
                int b2 = i >> 7, kq = i & 127;
                float4 v = (t >= 2) ? __ldcg((const float4*)&d_hid2[(b2*Tt + t - 2)*512 + kq*4])
                                    : make_float4(0.f,0.f,0.f,0.f);
                *(float4*)&Xs[b2*XP + (kq>>3)*SLC + (kq&7)*4] = v;
            }
            __syncthreads();
            mac2g(wt, 9, xrX, XP, 8, acc);      // W2B over h2(t-2)
            KS_REDUCE(acc);
            GM_STORE(acc);
            __syncthreads();
            if (tid < 256) {
                int b2 = tid >> 2, uu = tid & 3;
                int u = bb*4 + uu;
                float ig = Gm[b2*20 +  0 + uu] + Gm[1280 + b2*20 +  0 + uu] + bi2[0];
                float fg = Gm[b2*20 +  4 + uu] + Gm[1280 + b2*20 +  4 + uu] + bi2[1];
                float gg = Gm[b2*20 +  8 + uu] + Gm[1280 + b2*20 +  8 + uu] + bi2[2];
                float og = Gm[b2*20 + 12 + uu] + Gm[1280 + b2*20 + 12 + uu] + bi2[3];
                float c = sigf(fg)*d_c2[b2*512 + u] + sigf(ig)*tanhf(gg);
                float h = sigf(og)*tanhf(c);
                d_c2[b2*512 + u] = c;
                d_hid2[(b2*Tt + t - 1)*512 + u] = h;     // published at bar B
            }
        }
        BAR_WAIT();                   // A: h1(t) visible everywhere

        // attention(t): 5 components per block for batch ab
        {
            float* shh = At; float* pa = At+512; float* pb2 = At+520;
            float* pk = At+528; float* wsm = At+600;
            shh[tid] = __ldcg(&d_hid1[(ab*Tt + t)*512 + tid]);
            if (tid < 60) wsm[tid] = 0.f;
            __syncthreads();
            if (warp < 15) {
                int c = warp / 3, which = warp % 3;
                int o = which*10 + ah*5 + c;
                const float* wrow = &Wsw[o*512];
                float s = 0.f;
                #pragma unroll 4
                for (int k2 = lane; k2 < 512; k2 += 32) s += wrow[k2]*shh[k2];
                #pragma unroll
                for (int off = 16; off; off >>= 1) s += __shfl_down_sync(0xffffffffu, s, off);
                if (lane == 0) {
                    s = expf(s + bsw[o]);
                    if (which == 0)      pa[c]  = s;
                    else if (which == 1) pb2[c] = s;
                    else {
                        float kn = d_kbuf[ab*10 + ah*5 + c] + s;
                        pk[c] = kn;
                        d_kbuf[ab*10 + ah*5 + c] = kn;
                    }
                }
            }
            __syncthreads();
            if (tid < 64) {
                float uu = (float)tid, s = 0.f;
                #pragma unroll
                for (int c = 0; c < 5; c++) {
                    float d = pk[c] - uu;
                    s += pa[c]*expf(-pb2[c]*d*d);
                }
                s *= smask;
                atomicAdd(&wsm[chx], s);
            }
            __syncthreads();
            if (tid < 60) {
                float v = wsm[tid];
                if (ah == 0) d_wpA[ab*60 + tid] = v;
                else         d_wpB[ab*60 + tid] = v;
            }
        }
        BAR_ARRIVE();                 // B: w(t) + h2(t-1) published

        // X.h <- h1(t) (overlaps bar B wait)
        for (int i = tid; i < 8192; i += THR) {
            int b2 = i >> 7, kq = i & 127;
            *(float4*)&Xs[b2*XP + (kq>>3)*SLC + (kq&7)*4] =
                __ldcg((const float4*)&d_hid1[(b2*Tt + t)*512 + kq*4]);
        }
        BAR_WAIT();                   // B

        // misc1 <- [strk(t+1)|w(t)] ; M2 <- [strk(t)|w(t)]
        for (int i = tid; i < 4096; i += THR) {
            int b2 = i >> 6, e = i & 63;
            float wv = (e >= 3 && e < 63)
                     ? __ldcg(&d_wpA[b2*60 + e - 3]) + __ldcg(&d_wpB[b2*60 + e - 3]) : 0.f;
            float v1 = (e < 3) ? ((t + 1 < Tt) ? strks[(b2*Tt + t + 1)*3 + e] : 0.f) : wv;
            float v2 = (e < 3) ? strks[(b2*Tt + t)*3 + e] : wv;
            Xs[b2*XP + (e>>2)*SLC + 32 + (e&3)] = v1;
            M2s[b2*68 + e] = v2;
        }
        __syncthreads();
    }

    // ---------- epilogue: LSTM2 step 799 ----------
    ZERO_ACC(acc);
    mac2g(wt, 0, xrX, XP, 8, acc);          // X.h = h1(799)
    mac2g(wt, 8, xrM, 68, 1, acc);          // M2 = [strk(799)|w(799)]
    __syncthreads();
    for (int i = tid; i < 8192; i += THR) { // X.h <- h2(798)
        int b2 = i >> 7, kq = i & 127;
        *(float4*)&Xs[b2*XP + (kq>>3)*SLC + (kq&7)*4] =
            __ldcg((const float4*)&d_hid2[(b2*Tt + 798)*512 + kq*4]);
    }
    __syncthreads();
    mac2g(wt, 9, xrX, XP, 8, acc);
    KS_REDUCE(acc);
    GM_STORE(acc);
    __syncthreads();
    if (tid < 256) {
        int b2 = tid >> 2, uu = tid & 3;
        int u = bb*4 + uu;
        float ig = Gm[b2*20 +  0 + uu] + Gm[1280 + b2*20 +  0 + uu] + bi2[0];
        float fg = Gm[b2*20 +  4 + uu] + Gm[1280 + b2*20 +  4 + uu] + bi2[1];
        float gg = Gm[b2*20 +  8 + uu] + Gm[1280 + b2*20 +  8 + uu] + bi2[2];
        float og = Gm[b2*20 + 12 + uu] + Gm[1280 + b2*20 + 12 + uu] + bi2[3];
        float c = sigf(fg)*d_c2[b2*512 + u] + sigf(ig)*tanhf(gg);
        float h = sigf(og)*tanhf(c);
        d_hid2[(b2*Tt + 799)*512 + u] = h;
    }
}

// ---------------- MDN head ----------------
__global__ void mdn_kernel(const float* __restrict__ bmdn, float* __restrict__ out)
{
    __shared__ float rows[8*1024];
    __shared__ float pbuf[8*128];
    const int tid  = threadIdx.x;
    const int row0 = blockIdx.x*8;

    for (int idx = tid; idx < 8*1024; idx += 256) {
        int rr = idx >> 10, k2 = idx & 1023;
        int bt = row0 + rr;
        rows[idx] = (k2 < 512) ? d_hid1[bt*512 + k2] : d_hid2[bt*512 + (k2-512)];
    }
    __syncthreads();

    const int o    = tid & 127;
    const int half = tid >> 7;
    if (o < MDNO) {
        float acc[4];
        float bbv = bmdn[o];
        #pragma unroll
        for (int i = 0; i < 4; i++) acc[i] = bbv;
        const float* wr = &d_Weff[o*1024];
        for (int k2 = 0; k2 < 1024; k2 += 4) {
            float4 w = *(const float4*)(wr + k2);
            #pragma unroll
            for (int i = 0; i < 4; i++) {
                const float* x = &rows[(half*4 + i)*1024 + k2];
                acc[i] += w.x*x[0] + w.y*x[1] + w.z*x[2] + w.w*x[3];
            }
        }
        #pragma unroll
        for (int i = 0; i < 4; i++) pbuf[(half*4 + i)*128 + o] = acc[i];
    }
    __syncthreads();

    const int warp = tid >> 5, lane = tid & 31;
    const int bt = row0 + warp;
    const float* p = &pbuf[warp*128];

    float v = (lane < 20) ? p[lane] : -1e30f;
    float mx = v;
    #pragma unroll
    for (int off = 16; off; off >>= 1) mx = fmaxf(mx, __shfl_xor_sync(0xffffffffu, mx, off));
    float e = (lane < 20) ? expf(v - mx) : 0.f;
    float sum = e;
    #pragma unroll
    for (int off = 16; off; off >>= 1) sum += __shfl_xor_sync(0xffffffffu, sum, off);

    if (lane < 20) {
        float* base = out + BT;
        base[            bt*20 + lane] = e / sum;
        base[1*BT*20  +  bt*20 + lane] = p[20 + lane];
        base[2*BT*20  +  bt*20 + lane] = p[40 + lane];
        base[3*BT*20  +  bt*20 + lane] = expf(p[60 + lane]);
        base[4*BT*20  +  bt*20 + lane] = expf(p[80 + lane]);
        base[5*BT*20  +  bt*20 + lane] = tanhf(p[100 + lane]);
    }
    if (lane == 20) out[bt] = 1.f/(1.f + expf(-p[120]));
}

// ---------------- launch ----------------
extern "C" void kernel_launch(void* const* d_in, const int* in_sizes, int n_in,
                              void* d_out, int out_size)
{
    const float* strks   = (const float*)d_in[0];
    const float* sents_m = (const float*)d_in[3];
    const float* onehots = (const float*)d_in[4];
    const float* w_prev  = (const float*)d_in[5];
    const float* Wih1    = (const float*)d_in[6];
    const float* Whh1    = (const float*)d_in[7];
    const float* bih1    = (const float*)d_in[8];
    const float* bhh1    = (const float*)d_in[9];
    const float* Wih2    = (const float*)d_in[10];
    const float* Whh2    = (const float*)d_in[11];
    const float* bih2    = (const float*)d_in[12];
    const float* bhh2    = (const float*)d_in[13];
    const float* Wsw     = (const float*)d_in[14];
    const float* bsw     = (const float*)d_in[15];
    const float* Wmdn    = (const float*)d_in[16];
    const float* bmdn    = (const float*)d_in[17];
    float* out = (float*)d_out;

    cudaFuncSetAttribute(main_scan, cudaFuncAttributeMaxDynamicSharedMemorySize,
                         SM_TOT*sizeof(float));

    prep_pack1 <<<(NBLK*P1SZ  + 255)/256, 256>>>(Wih1, Whh1);
    prep_pack2w<<<(NBLK*P2WSZ + 255)/256, 256>>>(Wih2, Whh2);
    prep_misc  <<<(MDNO*1024 + 255)/256, 256>>>(bih1, bhh1, bih2, bhh2, Wmdn, w_prev);

    main_scan<<<NBLK, THR, SM_TOT*sizeof(float)>>>(strks, sents_m, onehots, Wsw, bsw);
    mdn_kernel<<<BT/8, 256>>>(bmdn, out);
}

// round 15
// speedup vs baseline: 1.3842x; 1.0221x over previous
#include <cuda_runtime.h>
#include <math.h>

// ---------------- problem constants ----------------
#define Bz   64
#define Tt   800
#define Hh   512
#define SENT 60
#define G4   2048
#define BT   (Bz*Tt)
#define MDNO 121
#define NBLK 128
#define THR  512

// X: per batch row, 16 slices x 36 words (h 32 + misc1 4), pitch 580 (%32==4)
#define XP   580
#define SLC  36
// W1 smem layout [ks][j][16 rows], slice stride %32==16 (conflict-free quarter-warp LDS.128)
#define P1KS 592             // 37*16
#define P1SZ (16*P1KS)       // 9472
// W2 gmem layout (streamed): float4 idx = ((c*4+r)*2 + kh)*32 + ksl*4 + rq ; 17 chunks
#define P2WSZ 17408          // floats per block

// dynamic smem (floats)
#define SM_W1 0
#define SM_X  9472           // 64*580 = 37120
#define SM_M2 (9472+37120)   // 64*68 = 4352
#define SM_G  (SM_M2+4352)   // 2*1280 = 2560 (attention scratch aliases)
#define SM_TOT (SM_G+2560)   // 53504 floats = 214016 B

// ---------------- persistent device scratch ----------------
__device__ float d_hid1[BT*Hh];
__device__ float d_hid2[BT*Hh];
__device__ float d_wpA [Bz*SENT];
__device__ float d_wpB [Bz*SENT];

__device__ float d_P1 [NBLK*P1SZ];
__device__ float d_P2w[NBLK*P2WSZ];
__device__ float d_b1p[G4];
__device__ float d_b2p[G4];
__device__ float d_Weff[MDNO*1024];

__device__ unsigned          d_cnt[2];
__device__ volatile unsigned d_epoch;

__device__ __forceinline__ float sigf(float x) { return 1.f/(1.f+expf(-x)); }

// ---------------- prep kernels ----------------
__global__ void prep_pack1(const float* __restrict__ Wih1, const float* __restrict__ Whh1) {
    int idx = blockIdx.x*blockDim.x + threadIdx.x;
    if (idx >= NBLK*P1SZ) return;
    int bb = idx / P1SZ, rem = idx % P1SZ;
    int ks = rem / P1KS, r2 = rem % P1KS;
    int j = r2 >> 4, rr = r2 & 15;
    int gate = rr >> 2, uu = rr & 3;
    int grow = gate*512 + bb*4 + uu;
    float v = 0.f;
    if (j < 32)      v = Whh1[grow*512 + ks*32 + j];          // recurrent h1
    else if (j < 36) { int e = ks*4 + (j-32);                  // misc [strk3|win60|pad]
                       if (e < 63) v = Wih1[grow*63 + e]; }
    d_P1[idx] = v;
}

// W2 streamed layout: chunks 0..7 = h1 part, 8 = misc2, 9..16 = h2 part
__global__ void prep_pack2w(const float* __restrict__ Wih2, const float* __restrict__ Whh2) {
    int idx = blockIdx.x*blockDim.x + threadIdx.x;
    if (idx >= NBLK*P2WSZ) return;
    int bb = idx / P2WSZ, rem = idx % P2WSZ;
    int f   = rem & 3;
    int i4  = rem >> 2;
    int rq  = i4 & 3;
    int ksl = (i4 >> 2) & 7;
    int kh  = (i4 >> 5) & 1;
    int cr  = i4 >> 6;
    int r   = cr & 3;
    int c   = cr >> 2;            // 0..16
    int ks  = kh*8 + ksl;
    int row16 = rq*4 + f;
    int gate = row16 >> 2, uu = row16 & 3;
    int grow = gate*512 + bb*4 + uu;
    float v = 0.f;
    if (c < 8)       v = Wih2[grow*575 + 3 + ks*32 + c*4 + r];
    else if (c == 8) {
        int e = ks*4 + r;
        if (e < 3)       v = Wih2[grow*575 + e];
        else if (e < 63) v = Wih2[grow*575 + 515 + (e-3)];
    }
    else             v = Whh2[grow*512 + ks*32 + (c-9)*4 + r];
    d_P2w[idx] = v;
}

__global__ void prep_misc(const float* __restrict__ bih1, const float* __restrict__ bhh1,
                          const float* __restrict__ bih2, const float* __restrict__ bhh2,
                          const float* __restrict__ Wmdn) {
    int idx = blockIdx.x*blockDim.x + threadIdx.x;
    if (idx < MDNO*1024) {
        int o = idx >> 10, k = idx & 1023;
        float v = Wmdn[o*1536 + k];
        if (k >= 512) v += Wmdn[o*1536 + k + 512];
        d_Weff[idx] = v;
    }
    if (idx < G4) {
        int bb = idx >> 4, rr = idx & 15;
        int gate = rr >> 2, uu = rr & 3;
        int grow = gate*512 + bb*4 + uu;
        d_b1p[idx] = bih1[grow] + bhh1[grow];
        d_b2p[idx] = bih2[grow] + bhh2[grow];
    }
    if (idx == 0) { d_cnt[0] = 0u; d_cnt[1] = 0u; d_epoch = 0u; }
}

// ---------------- split grid barrier ----------------
#define BAR_ARRIVE()                                                          \
    do {                                                                      \
        bseq++;                                                               \
        __syncthreads();                                                      \
        if (tid == 0) {                                                       \
            __threadfence();                                                  \
            if (atomicAdd(&d_cnt[bseq & 1u], 1u) == NBLK - 1u) {              \
                d_cnt[bseq & 1u] = 0u;                                        \
                __threadfence();                                              \
                d_epoch = bseq;                                               \
            }                                                                 \
        }                                                                     \
    } while (0)

#define BAR_WAIT()                                                            \
    do {                                                                      \
        if (tid == 0) {                                                       \
            while ((int)(d_epoch - bseq) < 0) __nanosleep(32);                \
        }                                                                     \
        __syncthreads();                                                      \
    } while (0)

// ---------------- MAC (smem weights): 4 rows x 8 batches per chunk of 4 k ----
__device__ __forceinline__ void mac_run(const float* __restrict__ xr,
                                        const float* __restrict__ wr,
                                        int chunks, float (&acc)[8][4])
{
    #pragma unroll 2
    for (int c = 0; c < chunks; c++) {
        int k = c*4;
        float4 w0 = *(const float4*)(wr + (k+0)*16);
        float4 w1 = *(const float4*)(wr + (k+1)*16);
        float4 w2 = *(const float4*)(wr + (k+2)*16);
        float4 w3 = *(const float4*)(wr + (k+3)*16);
        #pragma unroll
        for (int j = 0; j < 8; j++) {
            float4 xv = *(const float4*)(xr + j*XP + k);
            acc[j][0] = fmaf(w0.x, xv.x, fmaf(w1.x, xv.y, fmaf(w2.x, xv.z, fmaf(w3.x, xv.w, acc[j][0]))));
            acc[j][1] = fmaf(w0.y, xv.x, fmaf(w1.y, xv.y, fmaf(w2.y, xv.z, fmaf(w3.y, xv.w, acc[j][1]))));
            acc[j][2] = fmaf(w0.z, xv.x, fmaf(w1.z, xv.y, fmaf(w2.z, xv.z, fmaf(w3.z, xv.w, acc[j][2]))));
            acc[j][3] = fmaf(w0.w, xv.x, fmaf(w1.w, xv.y, fmaf(w2.w, xv.z, fmaf(w3.w, xv.w, acc[j][3]))));
        }
    }
}

// ---------------- MAC (gmem-streamed weights) ----------------
__device__ __forceinline__ void mac2g(const float4* __restrict__ wt, int c0,
                                      const float* __restrict__ xr, int xpitch,
                                      int nch, float (&acc)[8][4])
{
    #pragma unroll 4
    for (int c = 0; c < nch; c++) {
        const float4* wp = wt + (c0 + c)*256;
        float4 w0 = __ldcg(wp);
        float4 w1 = __ldcg(wp + 64);
        float4 w2 = __ldcg(wp + 128);
        float4 w3 = __ldcg(wp + 192);
        #pragma unroll
        for (int j = 0; j < 8; j++) {
            float4 xv = *(const float4*)(xr + j*xpitch + c*4);
            acc[j][0] = fmaf(w0.x, xv.x, fmaf(w1.x, xv.y, fmaf(w2.x, xv.z, fmaf(w3.x, xv.w, acc[j][0]))));
            acc[j][1] = fmaf(w0.y, xv.x, fmaf(w1.y, xv.y, fmaf(w2.y, xv.z, fmaf(w3.y, xv.w, acc[j][1]))));
            acc[j][2] = fmaf(w0.z, xv.x, fmaf(w1.z, xv.y, fmaf(w2.z, xv.z, fmaf(w3.z, xv.w, acc[j][2]))));
            acc[j][3] = fmaf(w0.w, xv.x, fmaf(w1.w, xv.y, fmaf(w2.w, xv.z, fmaf(w3.w, xv.w, acc[j][3]))));
        }
    }
}

#define ZERO_ACC(acc)                                                         \
    do { _Pragma("unroll") for (int j = 0; j < 8; j++)                        \
         { _Pragma("unroll") for (int i = 0; i < 4; i++) acc[j][i] = 0.f; } } while (0)

#define KS_REDUCE(acc)                                                        \
    do {                                                                      \
        _Pragma("unroll")                                                     \
        for (int off = 4; off <= 16; off <<= 1) {                             \
            _Pragma("unroll")                                                 \
            for (int j = 0; j < 8; j++) {                                     \
                _Pragma("unroll")                                             \
                for (int i = 0; i < 4; i++)                                   \
                    acc[j][i] += __shfl_xor_sync(0xffffffffu, acc[j][i], off);\
            }                                                                 \
        }                                                                     \
    } while (0)

#define GM_STORE(acc)                                                         \
    do { if (lane < 4) {                                                      \
        _Pragma("unroll")                                                     \
        for (int j = 0; j < 8; j++)                                           \
            *(float4*)&Gm[kh*1280 + (b0+j)*20 + rq*4] =                       \
                make_float4(acc[j][0], acc[j][1], acc[j][2], acc[j][3]);      \
    } } while (0)

// ---------------- persistent main kernel ----------------
extern __shared__ float sm[];

__global__ void __launch_bounds__(THR, 1)
main_scan(const float* __restrict__ strks,
          const float* __restrict__ sents_m,
          const float* __restrict__ onehots,
          const float* __restrict__ w_prev,
          const float* __restrict__ Wsw,
          const float* __restrict__ bsw)
{
    float* W1  = sm + SM_W1;
    float* Xs  = sm + SM_X;
    float* M2s = sm + SM_M2;
    float* Gm  = sm + SM_G;          // [2][64*20]
    float* At  = Gm;                 // attn scratch: shh 512 | pa@512 | pb@520 | pk@528 | wsm@600

    const int tid  = threadIdx.x;
    const int bb   = blockIdx.x;
    const int warp = tid >> 5, lane = tid & 31;
    const int oct  = warp >> 1, kh = warp & 1;
    const int ksl  = lane >> 2, rq = lane & 3;
    const int ks   = kh*8 + ksl;
    const int b0   = oct*8;
    unsigned bseq = 0;

    const int ab = bb & 63;          // attention batch
    const int ah = bb >> 6;          // attention half (components ah*5..ah*5+4)

    int chx = 0; float smask = 0.f;
    if (tid < 64) {
        smask = sents_m[ab*64 + tid];
        const float* oh = onehots + (ab*64 + tid)*60;
        for (int c = 0; c < 60; c++) if (oh[c] > 0.5f) chx = c;
    }

    // cell-update thread constants + register-resident cell states
    const int cb = tid >> 2, cu = tid & 3;     // batch, unit-within-quad (tid<256)
    const int cuu = bb*4 + cu;                 // global hidden unit
    float c1r = 0.f, c2r = 0.f;
    float bi1[4], bi2[4];
    #pragma unroll
    for (int g = 0; g < 4; g++) {
        bi1[g] = d_b1p[bb*16 + g*4 + cu];
        bi2[g] = d_b2p[bb*16 + g*4 + cu];
    }

    float knr = 0.f;                           // kappa register (lane0 of kappa warps)

    const float*  xrX = Xs  + b0*XP + ks*SLC;
    const float*  xrM = M2s + b0*68 + ks*4;
    const float*  wr1 = W1  + ks*P1KS + rq*4;
    const float4* wt  = (const float4*)d_P2w + (size_t)bb*(P2WSZ/4) + kh*32 + ksl*4 + rq;

    float acc[8][4];

    // ---------- prologue ----------
    {
        const float4* src = (const float4*)(d_P1 + bb*P1SZ);
        for (int i = tid; i < P1SZ/4; i += THR) ((float4*)W1)[i] = src[i];
    }
    for (int i = tid; i < 8192; i += THR) {                       // X.h = 0
        int b2 = i >> 7, kq = i & 127;
        *(float4*)&Xs[b2*XP + (kq>>3)*SLC + (kq&7)*4] = make_float4(0.f,0.f,0.f,0.f);
    }
    for (int i = tid; i < 4096; i += THR) {                       // misc1 = [strk(0)|w_prev]
        int b2 = i >> 6, e = i & 63;
        float v = 0.f;
        if (e < 3)       v = strks[(b2*Tt + 0)*3 + e];
        else if (e < 63) v = w_prev[b2*60 + e - 3];
        Xs[b2*XP + (e>>2)*SLC + 32 + (e&3)] = v;
    }
    __syncthreads();
    ZERO_ACC(acc);                   // MAC1-rec(0) over h1(-1)=0

    // ---------- merged scan ----------
    for (int t = 0; t < Tt; t++) {
        // 1. finish LSTM1 gates(t): misc chunk (rec part carried in acc)
        mac_run(xrX + 32, wr1 + 32*16, 1, acc);
        KS_REDUCE(acc);
        GM_STORE(acc);
        __syncthreads();
        if (tid < 256) {
            float ig = Gm[cb*20 +  0 + cu] + Gm[1280 + cb*20 +  0 + cu] + bi1[0];
            float fg = Gm[cb*20 +  4 + cu] + Gm[1280 + cb*20 +  4 + cu] + bi1[1];
            float gg = Gm[cb*20 +  8 + cu] + Gm[1280 + cb*20 +  8 + cu] + bi1[2];
            float og = Gm[cb*20 + 12 + cu] + Gm[1280 + cb*20 + 12 + cu] + bi1[3];
            c1r = sigf(fg)*c1r + sigf(ig)*tanhf(gg);
            d_hid1[(cb*Tt + t)*512 + cuu] = sigf(og)*tanhf(c1r);
        }
        BAR_ARRIVE();                 // A: h1(t) ready

        // 2. LSTM2 gates(t-1) — hides bar A skew
        if (t > 0) {
            ZERO_ACC(acc);
            mac2g(wt, 0, xrX, XP, 8, acc);      // W2A over X.h = h1(t-1)
            mac2g(wt, 8, xrM, 68, 1, acc);      // misc2(t-1)
            __syncthreads();                     // all done reading X.h
            for (int i = tid; i < 8192; i += THR) {   // X.h <- h2(t-2)
                int b2 = i >> 7, kq = i & 127;
                float4 v = (t >= 2) ? __ldcg((const float4*)&d_hid2[(b2*Tt + t - 2)*512 + kq*4])
                                    : make_float4(0.f,0.f,0.f,0.f);
                *(float4*)&Xs[b2*XP + (kq>>3)*SLC + (kq&7)*4] = v;
            }
            __syncthreads();
            mac2g(wt, 9, xrX, XP, 8, acc);      // W2B over h2(t-2)
            KS_REDUCE(acc);
            GM_STORE(acc);
            __syncthreads();
            if (tid < 256) {
                float ig = Gm[cb*20 +  0 + cu] + Gm[1280 + cb*20 +  0 + cu] + bi2[0];
                float fg = Gm[cb*20 +  4 + cu] + Gm[1280 + cb*20 +  4 + cu] + bi2[1];
                float gg = Gm[cb*20 +  8 + cu] + Gm[1280 + cb*20 +  8 + cu] + bi2[2];
                float og = Gm[cb*20 + 12 + cu] + Gm[1280 + cb*20 + 12 + cu] + bi2[3];
                c2r = sigf(fg)*c2r + sigf(ig)*tanhf(gg);
                d_hid2[(cb*Tt + t - 1)*512 + cuu] = sigf(og)*tanhf(c2r);  // covered by bar B
            }
        }
        BAR_WAIT();                   // A: h1(t) visible everywhere

        // 3. attention(t): 5 components per block for batch ab
        {
            float* shh = At; float* pa = At+512; float* pb2 = At+520;
            float* pk = At+528; float* wsm = At+600;
            shh[tid] = __ldcg(&d_hid1[(ab*Tt + t)*512 + tid]);
            if (tid < 60) wsm[tid] = 0.f;
            __syncthreads();
            if (warp < 15) {
                int c = warp / 3, which = warp % 3;
                int o = which*10 + ah*5 + c;
                const float* wrow = &Wsw[o*512];
                float s = 0.f;
                #pragma unroll 4
                for (int k2 = lane; k2 < 512; k2 += 32) s += wrow[k2]*shh[k2];
                #pragma unroll
                for (int off = 16; off; off >>= 1) s += __shfl_down_sync(0xffffffffu, s, off);
                if (lane == 0) {
                    s = expf(s + bsw[o]);
                    if (which == 0)      pa[c]  = s;
                    else if (which == 1) pb2[c] = s;
                    else { knr += s; pk[c] = knr; }      // kappa in register
                }
            }
            __syncthreads();
            if (tid < 64) {
                float uu = (float)tid, s = 0.f;
                #pragma unroll
                for (int c = 0; c < 5; c++) {
                    float d = pk[c] - uu;
                    s += pa[c]*expf(-pb2[c]*d*d);
                }
                s *= smask;
                atomicAdd(&wsm[chx], s);
            }
            __syncthreads();
            if (tid < 60) {
                float v = wsm[tid];
                if (ah == 0) d_wpA[ab*60 + tid] = v;
                else         d_wpB[ab*60 + tid] = v;
            }
        }
        BAR_ARRIVE();                 // B: w(t) + h2(t-1) published

        // 4. X.h <- h1(t) ; MAC1-rec(t+1) — both hide bar B wait
        for (int i = tid; i < 8192; i += THR) {
            int b2 = i >> 7, kq = i & 127;
            *(float4*)&Xs[b2*XP + (kq>>3)*SLC + (kq&7)*4] =
                __ldcg((const float4*)&d_hid1[(b2*Tt + t)*512 + kq*4]);
        }
        __syncthreads();
        ZERO_ACC(acc);
        if (t + 1 < Tt) mac_run(xrX, wr1, 8, acc);
        BAR_WAIT();                   // B

        // 5. misc1 <- [strk(t+1)|w(t)] ; M2 <- [strk(t)|w(t)]
        for (int i = tid; i < 4096; i += THR) {
            int b2 = i >> 6, e = i & 63;
            float wv = (e >= 3 && e < 63)
                     ? __ldcg(&d_wpA[b2*60 + e - 3]) + __ldcg(&d_wpB[b2*60 + e - 3]) : 0.f;
            float v1 = (e < 3) ? ((t + 1 < Tt) ? strks[(b2*Tt + t + 1)*3 + e] : 0.f) : wv;
            float v2 = (e < 3) ? strks[(b2*Tt + t)*3 + e] : wv;
            Xs[b2*XP + (e>>2)*SLC + 32 + (e&3)] = v1;
            M2s[b2*68 + e] = v2;
        }
        __syncthreads();
    }

    // ---------- epilogue: LSTM2 step 799 ----------
    ZERO_ACC(acc);
    mac2g(wt, 0, xrX, XP, 8, acc);          // X.h = h1(799)
    mac2g(wt, 8, xrM, 68, 1, acc);          // M2 = [strk(799)|w(799)]
    __syncthreads();
    for (int i = tid; i < 8192; i += THR) { // X.h <- h2(798)
        int b2 = i >> 7, kq = i & 127;
        *(float4*)&Xs[b2*XP + (kq>>3)*SLC + (kq&7)*4] =
            __ldcg((const float4*)&d_hid2[(b2*Tt + 798)*512 + kq*4]);
    }
    __syncthreads();
    mac2g(wt, 9, xrX, XP, 8, acc);
    KS_REDUCE(acc);
    GM_STORE(acc);
    __syncthreads();
    if (tid < 256) {
        float ig = Gm[cb*20 +  0 + cu] + Gm[1280 + cb*20 +  0 + cu] + bi2[0];
        float fg = Gm[cb*20 +  4 + cu] + Gm[1280 + cb*20 +  4 + cu] + bi2[1];
        float gg = Gm[cb*20 +  8 + cu] + Gm[1280 + cb*20 +  8 + cu] + bi2[2];
        float og = Gm[cb*20 + 12 + cu] + Gm[1280 + cb*20 + 12 + cu] + bi2[3];
        float c = sigf(fg)*c2r + sigf(ig)*tanhf(gg);
        d_hid2[(cb*Tt + 799)*512 + cuu] = sigf(og)*tanhf(c);
    }
}

// ---------------- MDN head ----------------
__global__ void mdn_kernel(const float* __restrict__ bmdn, float* __restrict__ out)
{
    __shared__ float rows[8*1024];
    __shared__ float pbuf[8*128];
    const int tid  = threadIdx.x;
    const int row0 = blockIdx.x*8;

    for (int idx = tid; idx < 8*1024; idx += 256) {
        int rr = idx >> 10, k2 = idx & 1023;
        int bt = row0 + rr;
        rows[idx] = (k2 < 512) ? d_hid1[bt*512 + k2] : d_hid2[bt*512 + (k2-512)];
    }
    __syncthreads();

    const int o    = tid & 127;
    const int half = tid >> 7;
    if (o < MDNO) {
        float acc[4];
        float bbv = bmdn[o];
        #pragma unroll
        for (int i = 0; i < 4; i++) acc[i] = bbv;
        const float* wr = &d_Weff[o*1024];
        for (int k2 = 0; k2 < 1024; k2 += 4) {
            float4 w = *(const float4*)(wr + k2);
            #pragma unroll
            for (int i = 0; i < 4; i++) {
                const float* x = &rows[(half*4 + i)*1024 + k2];
                acc[i] += w.x*x[0] + w.y*x[1] + w.z*x[2] + w.w*x[3];
            }
        }
        #pragma unroll
        for (int i = 0; i < 4; i++) pbuf[(half*4 + i)*128 + o] = acc[i];
    }
    __syncthreads();

    const int warp = tid >> 5, lane = tid & 31;
    const int bt = row0 + warp;
    const float* p = &pbuf[warp*128];

    float v = (lane < 20) ? p[lane] : -1e30f;
    float mx = v;
    #pragma unroll
    for (int off = 16; off; off >>= 1) mx = fmaxf(mx, __shfl_xor_sync(0xffffffffu, mx, off));
    float e = (lane < 20) ? expf(v - mx) : 0.f;
    float sum = e;
    #pragma unroll
    for (int off = 16; off; off >>= 1) sum += __shfl_xor_sync(0xffffffffu, sum, off);

    if (lane < 20) {
        float* base = out + BT;
        base[            bt*20 + lane] = e / sum;
        base[1*BT*20  +  bt*20 + lane] = p[20 + lane];
        base[2*BT*20  +  bt*20 + lane] = p[40 + lane];
        base[3*BT*20  +  bt*20 + lane] = expf(p[60 + lane]);
        base[4*BT*20  +  bt*20 + lane] = expf(p[80 + lane]);
        base[5*BT*20  +  bt*20 + lane] = tanhf(p[100 + lane]);
    }
    if (lane == 20) out[bt] = 1.f/(1.f + expf(-p[120]));
}

// ---------------- launch ----------------
extern "C" void kernel_launch(void* const* d_in, const int* in_sizes, int n_in,
                              void* d_out, int out_size)
{
    const float* strks   = (const float*)d_in[0];
    const float* sents_m = (const float*)d_in[3];
    const float* onehots = (const float*)d_in[4];
    const float* w_prev  = (const float*)d_in[5];
    const float* Wih1    = (const float*)d_in[6];
    const float* Whh1    = (const float*)d_in[7];
    const float* bih1    = (const float*)d_in[8];
    const float* bhh1    = (const float*)d_in[9];
    const float* Wih2    = (const float*)d_in[10];
    const float* Whh2    = (const float*)d_in[11];
    const float* bih2    = (const float*)d_in[12];
    const float* bhh2    = (const float*)d_in[13];
    const float* Wsw     = (const float*)d_in[14];
    const float* bsw     = (const float*)d_in[15];
    const float* Wmdn    = (const float*)d_in[16];
    const float* bmdn    = (const float*)d_in[17];
    float* out = (float*)d_out;

    cudaFuncSetAttribute(main_scan, cudaFuncAttributeMaxDynamicSharedMemorySize,
                         SM_TOT*sizeof(float));

    prep_pack1 <<<(NBLK*P1SZ  + 255)/256, 256>>>(Wih1, Whh1);
    prep_pack2w<<<(NBLK*P2WSZ + 255)/256, 256>>>(Wih2, Whh2);
    prep_misc  <<<(MDNO*1024 + 255)/256, 256>>>(bih1, bhh1, bih2, bhh2, Wmdn);

    main_scan<<<NBLK, THR, SM_TOT*sizeof(float)>>>(strks, sents_m, onehots, w_prev, Wsw, bsw);
    mdn_kernel<<<BT/8, 256>>>(bmdn, out);
}